// round 5
// baseline (speedup 1.0000x reference)
#include <cuda_runtime.h>

#define KC 400
#define D 64
#define TPB 128
#define ROWS_PER_THREAD 2
#define KCHUNK 200
#define NCHUNKS 2

// packed fp32x2 ops (sm_100+), elementwise .rn — bit-identical to 2x scalar fmaf/fadd.
__device__ __forceinline__ void fma2(unsigned long long &acc, unsigned long long a,
                                     unsigned long long b) {
    asm("fma.rn.f32x2 %0, %1, %2, %0;" : "+l"(acc) : "l"(a), "l"(b));
}
__device__ __forceinline__ unsigned long long add2(unsigned long long a, unsigned long long b) {
    unsigned long long r;
    asm("add.rn.f32x2 %0, %1, %2;" : "=l"(r) : "l"(a), "l"(b));
    return r;
}
__device__ __forceinline__ void unpack2(unsigned long long v, float &lo, float &hi) {
    asm("mov.b64 {%0, %1}, %2;" : "=f"(lo), "=f"(hi) : "l"(v));
}
__device__ __forceinline__ unsigned long long pack2(float lo, float hi) {
    unsigned long long r;
    asm("mov.b64 %0, {%1, %2};" : "=l"(r) : "f"(lo), "f"(hi));
    return r;
}

__global__ void __launch_bounds__(TPB, 3)
vq_argmin_kernel(const float* __restrict__ x, const float* __restrict__ emb,
                 float* __restrict__ out, int nrows) {
    extern __shared__ float smem[];
    float*              s_e  = smem;                                       // [KCHUNK*D] chunk of codes
    unsigned long long* s_n2 = (unsigned long long*)(smem + KCHUNK * D);   // [KC] packed (-0.5||e||^2, 0)

    // all 400 norms, once, from gmem (L2-hot after first block)
    for (int k = threadIdx.x; k < KC; k += TPB) {
        const float* e = emb + k * D;
        float s = 0.f;
        #pragma unroll 16
        for (int d = 0; d < D; d++) s = fmaf(e[d], e[d], s);
        s_n2[k] = pack2(-0.5f * s, 0.0f);
    }

    // two rows per thread, strided by TPB (coalesced-ish LDG/STG per warp)
    int row0 = blockIdx.x * (TPB * ROWS_PER_THREAD) + threadIdx.x;
    int row1 = row0 + TPB;
    bool valid = (row0 < nrows);
    if (row1 >= nrows) row1 = row0 < nrows ? row0 : 0;   // no early return (syncthreads below)
    if (!valid) row0 = 0;

    // both rows in registers: 16 ulonglong2 (= 64 floats) each
    ulonglong2 x0[16], x1[16];
    const ulonglong2* p0 = reinterpret_cast<const ulonglong2*>(x + (size_t)row0 * D);
    const ulonglong2* p1 = reinterpret_cast<const ulonglong2*>(x + (size_t)row1 * D);
    #pragma unroll
    for (int i = 0; i < 16; i++) { x0[i] = p0[i]; x1[i] = p1[i]; }

    const ulonglong2* se2 = reinterpret_cast<const ulonglong2*>(s_e);

    // maximize score = x.e - 0.5*||e||^2  (== argmin squared L2; ||x||^2 row-constant)
    float best0 = -3.4e38f, best1 = -3.4e38f;
    int bk0 = 0, bk1 = 0;

    for (int cb = 0; cb < KC; cb += KCHUNK) {
        __syncthreads();   // previous chunk's readers done before overwrite
        // stage this chunk of the codebook (coalesced float4)
        const float4* src = reinterpret_cast<const float4*>(emb + cb * D);
        float4* dst = reinterpret_cast<float4*>(s_e);
        for (int i = threadIdx.x; i < KCHUNK * D / 4; i += TPB) dst[i] = src[i];
        __syncthreads();

        #pragma unroll 2
        for (int k = 0; k < KCHUNK; k++) {
            unsigned long long n = s_n2[cb + k];      // broadcast LDS.64
            unsigned long long a0 = n, a1 = 0ull;     // row0: 2 chains
            unsigned long long b0 = n, b1 = 0ull;     // row1: 2 chains
            const ulonglong2* e2 = se2 + k * 16;      // 8 broadcast LDS.128
            #pragma unroll
            for (int i = 0; i < 16; i += 2) {
                ulonglong2 ea = e2[i];
                ulonglong2 eb = e2[i + 1];
                fma2(a0, x0[i].x, ea.x);     fma2(a1, x0[i].y, ea.y);
                fma2(b0, x1[i].x, ea.x);     fma2(b1, x1[i].y, ea.y);
                fma2(a0, x0[i + 1].x, eb.x); fma2(a1, x0[i + 1].y, eb.y);
                fma2(b0, x1[i + 1].x, eb.x); fma2(b1, x1[i + 1].y, eb.y);
            }
            unsigned long long sa = add2(a0, a1);
            unsigned long long sb = add2(b0, b1);
            float lo, hi;
            unpack2(sa, lo, hi);
            float sc0 = lo + hi;
            unpack2(sb, lo, hi);
            float sc1 = lo + hi;
            int kg = cb + k;
            if (sc0 > best0) { best0 = sc0; bk0 = kg; }   // strict >: first-max == jnp first-min
            if (sc1 > best1) { best1 = sc1; bk1 = kg; }
        }
    }

    if (!valid) return;

    // gather winning codes from gmem (codebook is L2-resident), write out
    {
        const float4* cp = reinterpret_cast<const float4*>(emb + (size_t)bk0 * D);
        float4* op = reinterpret_cast<float4*>(out + (size_t)row0 * D);
        #pragma unroll
        for (int i = 0; i < 16; i++) op[i] = cp[i];
    }
    if (row1 != row0) {
        const float4* cp = reinterpret_cast<const float4*>(emb + (size_t)bk1 * D);
        float4* op = reinterpret_cast<float4*>(out + (size_t)row1 * D);
        #pragma unroll
        for (int i = 0; i < 16; i++) op[i] = cp[i];
    }
}

extern "C" void kernel_launch(void* const* d_in, const int* in_sizes, int n_in,
                              void* d_out, int out_size) {
    const float* x   = (const float*)d_in[0];
    const float* emb = (const float*)d_in[1];
    float* out = (float*)d_out;

    int nrows = in_sizes[0] / D;   // 262144
    int smem_bytes = KCHUNK * D * (int)sizeof(float) + KC * (int)sizeof(unsigned long long); // 54400 B

    cudaFuncSetAttribute(vq_argmin_kernel,
                         cudaFuncAttributeMaxDynamicSharedMemorySize, smem_bytes);

    int rows_per_block = TPB * ROWS_PER_THREAD;
    int blocks = (nrows + rows_per_block - 1) / rows_per_block;   // 1024
    vq_argmin_kernel<<<blocks, TPB, smem_bytes>>>(x, emb, out, nrows);
}